// round 15
// baseline (speedup 1.0000x reference)
#include <cuda_runtime.h>
#include <cuda_fp16.h>
#include <cstdint>

// ============================================================================
// S6 forward, reduced:
//   y[t,d] = x[t,d] * softplus(U1[t,d] + b1[d]) * s[t]
//   s[t]   = sum_n (U2[t,n]+b2[n]) * (U3[t,n]+b3[n])
// Pipeline (fp16 mma.sync, fp32 accum; base sm_103 ISA — no tcgen05):
//   1. prep+packW1 (ONE kernel): blocks [0,512) = x->fp16 + s[t], reading
//      W2/W3 directly (L2-resident) — no pack_w23 kernel, no g_W23h;
//      blocks [512,768) = W1 fp32->fp16 copy (overlapped)
//   2. gemm: 128x128 CTA, 4 warps @ 64x64, A ldmatrix / B ldmatrix.trans,
//            3-stage cp.async, fused epilogue -> y
// ============================================================================

#define NTOK   8192
#define DDIM   1024

#define BM     128
#define BN     128
#define BK     32
#define NKIT   (DDIM / BK)   // 32
#define GTHREADS 128         // 4 warps, 2x2 warp grid, 64x64 per warp

#define PITCH_H   40         // A smem row pitch (halves) = 80B
#define B_PITCH_H 136        // B smem row pitch (halves) = 272B; trans-ldm conflict-free
#define A_STAGE_H (BM * PITCH_H)               // 5120 halves
#define B_STAGE_H (BK * B_PITCH_H)             // 4352 halves
#define G_STAGE_H (A_STAGE_H + B_STAGE_H)      // 9472
#define STAGES    3
#define G_SMEM_BYTES (STAGES * G_STAGE_H * 2)  // 56832

#define PREP_BLOCKS 512
#define COPY_BLOCKS 256       // 262144 float4 / 1024 per block

__device__ __half g_W1h[(size_t)DDIM * DDIM];  // W1, [k][n], fp16, 2 MB
__device__ __half g_Xh[(size_t)NTOK * DDIM];   // x fp16, 16.8 MB
__device__ float  g_s[NTOK];

// ---------------------------------------------------------------------------
// helpers
// ---------------------------------------------------------------------------
__device__ __forceinline__ uint32_t smem_u32(const void* p) {
    uint32_t a;
    asm("{ .reg .u64 t; cvta.to.shared.u64 t, %1; cvt.u32.u64 %0, t; }" : "=r"(a) : "l"(p));
    return a;
}
__device__ __forceinline__ uint32_t h2_u32(__half2 h) {
    union { __half2 h; uint32_t u; } cvt;
    cvt.h = h;
    return cvt.u;
}
__device__ __forceinline__ void cp_async16(uint32_t dst, const void* src) {
    asm volatile("cp.async.cg.shared.global [%0], [%1], 16;" :: "r"(dst), "l"(src) : "memory");
}
__device__ __forceinline__ void cp_commit() {
    asm volatile("cp.async.commit_group;" ::: "memory");
}
template <int N>
__device__ __forceinline__ void cp_wait() {
    asm volatile("cp.async.wait_group %0;" :: "n"(N) : "memory");
}
__device__ __forceinline__ void ldmx4(uint32_t* r, uint32_t addr) {
    asm volatile("ldmatrix.sync.aligned.m8n8.x4.shared.b16 {%0,%1,%2,%3}, [%4];"
        : "=r"(r[0]), "=r"(r[1]), "=r"(r[2]), "=r"(r[3]) : "r"(addr));
}
__device__ __forceinline__ void ldmx4t(uint32_t* r, uint32_t addr) {
    asm volatile("ldmatrix.sync.aligned.m8n8.x4.trans.shared.b16 {%0,%1,%2,%3}, [%4];"
        : "=r"(r[0]), "=r"(r[1]), "=r"(r[2]), "=r"(r[3]) : "r"(addr));
}
__device__ __forceinline__ void mma_f16(float* c, const uint32_t* a, const uint32_t* b) {
    asm volatile(
        "mma.sync.aligned.m16n8k16.row.col.f32.f16.f16.f32 "
        "{%0,%1,%2,%3}, {%4,%5,%6,%7}, {%8,%9}, {%0,%1,%2,%3};"
        : "+f"(c[0]), "+f"(c[1]), "+f"(c[2]), "+f"(c[3])
        : "r"(a[0]), "r"(a[1]), "r"(a[2]), "r"(a[3]), "r"(b[0]), "r"(b[1]));
}
__device__ __forceinline__ float softplus_f(float z) {
    return fmaxf(z, 0.0f) + __logf(1.0f + __expf(-fabsf(z)));
}

// ---------------------------------------------------------------------------
// Kernel 1: prep + W1 pack, one launch.
//   blocks [0,512):   x->fp16 convert + s[t], 16 tokens each; W2/W3 read
//                     directly per chunk (L2-resident), converted in-CTA
//   blocks [512,768): W1 fp32->fp16 copy, 4 float4 per thread
// ---------------------------------------------------------------------------
#define P_PITCH 136
#define PX_STG  (16 * P_PITCH)
#define PW_STG  (32 * P_PITCH)

__global__ void __launch_bounds__(256) s6_prep(const float* __restrict__ x,
                                               const float* __restrict__ W1,
                                               const float* __restrict__ W2,
                                               const float* __restrict__ W3,
                                               const float* __restrict__ b2,
                                               const float* __restrict__ b3) {
    __shared__ __half sX[PX_STG];
    __shared__ __half sW[PW_STG];
    __shared__ float sU[16][33];

    const int tid = threadIdx.x;

    if (blockIdx.x >= PREP_BLOCKS) {
        // ---- W1 copy path (overlaps prep blocks) ----
        const int rel = blockIdx.x - PREP_BLOCKS;
#pragma unroll
        for (int i = 0; i < 4; ++i) {
            const size_t i4 = (size_t)rel * 1024 + i * 256 + tid;
            const float4 v = ((const float4*)W1)[i4];
            uint2 pk;
            pk.x = h2_u32(__float22half2_rn(make_float2(v.x, v.y)));
            pk.y = h2_u32(__float22half2_rn(make_float2(v.z, v.w)));
            ((uint2*)g_W1h)[i4] = pk;
        }
        return;
    }

    // ---- prep path ----
    const int wid = tid >> 5;
    const int lane = tid & 31;
    const int grp = lane >> 2;
    const int qid = lane & 3;
    const int tok0 = blockIdx.x * 16;

    for (int i = tid; i < 16 * 33; i += 256) ((float*)sU)[i] = 0.0f;

    const int t = tid >> 4;            // token row (0..15) for x convert
    const int co = (tid & 15) * 8;     // col offset within chunk

    // W fill decomposition (per chunk): 1024 float4 reads, 4 per thread
    const int wk[4] = { (tid) & 511, (tid + 256) & 511,
                        (tid + 512) & 511, (tid + 768) & 511 };

    float acc[4][4];
#pragma unroll
    for (int g = 0; g < 4; ++g)
#pragma unroll
        for (int q = 0; q < 4; ++q) acc[g][q] = 0.0f;

    for (int c = 0; c < 8; ++c) {
        // ---- x chunk: load fp32, convert, store to sX + g_Xh ----
        const float* src = x + (size_t)(tok0 + t) * DDIM + c * 128 + co;
        float4 v0 = *(const float4*)(src + 0);
        float4 v1 = *(const float4*)(src + 4);
        uint4 pk;
        pk.x = h2_u32(__float22half2_rn(make_float2(v0.x, v0.y)));
        pk.y = h2_u32(__float22half2_rn(make_float2(v0.z, v0.w)));
        pk.z = h2_u32(__float22half2_rn(make_float2(v1.x, v1.y)));
        pk.w = h2_u32(__float22half2_rn(make_float2(v1.z, v1.w)));
        *(uint4*)(&sX[t * P_PITCH + co]) = pk;
        *(uint4*)(g_Xh + (size_t)(tok0 + t) * DDIM + c * 128 + co) = pk;

        // ---- W2/W3 chunk: direct load (L2-hit), convert, transpose to sW ----
#pragma unroll
        for (int j = 0; j < 4; ++j) {
            const int idx = tid + j * 256;          // 0..1023
            const int fidx = idx & 511;
            const int kl = fidx >> 2;               // chunk-local k (0..127)
            const int nq = fidx & 3;                // n quad
            const float* wsrc = ((idx < 512) ? W2 : W3)
                                + (size_t)(c * 128 + kl) * 16 + nq * 4;
            const float4 wv = *(const float4*)wsrc;
            const int nb = ((idx < 512) ? 0 : 16) + nq * 4;
            sW[(nb + 0) * P_PITCH + kl] = __float2half_rn(wv.x);
            sW[(nb + 1) * P_PITCH + kl] = __float2half_rn(wv.y);
            sW[(nb + 2) * P_PITCH + kl] = __float2half_rn(wv.z);
            sW[(nb + 3) * P_PITCH + kl] = __float2half_rn(wv.w);
        }

        __syncthreads();   // sX, sW ready

        // ---- mma: warp `wid` handles k16 slice wid of the chunk; M=16, N=32
        const int koff = wid * 16 + 2 * qid;
        {
            const __half* p = &sX[grp * P_PITCH + koff];
            uint32_t a[4];
            a[0] = *(const uint32_t*)p;
            a[1] = *(const uint32_t*)(p + 8 * P_PITCH);
            a[2] = *(const uint32_t*)(p + 8);
            a[3] = *(const uint32_t*)(p + 8 * P_PITCH + 8);
#pragma unroll
            for (int g = 0; g < 4; ++g) {
                const __half* q = &sW[(g * 8 + grp) * P_PITCH + koff];
                uint32_t b[2];
                b[0] = *(const uint32_t*)q;
                b[1] = *(const uint32_t*)(q + 8);
                mma_f16(acc[g], a, b);
            }
        }
        __syncthreads();   // protect sX/sW rewrite at c+1
    }

    // cross-warp reduce via smem atomics
#pragma unroll
    for (int g = 0; g < 4; ++g) {
        atomicAdd(&sU[grp][g * 8 + 2 * qid],         acc[g][0]);
        atomicAdd(&sU[grp][g * 8 + 2 * qid + 1],     acc[g][1]);
        atomicAdd(&sU[grp + 8][g * 8 + 2 * qid],     acc[g][2]);
        atomicAdd(&sU[grp + 8][g * 8 + 2 * qid + 1], acc[g][3]);
    }
    __syncthreads();

    if (tid < 16) {
        float s = 0.0f;
#pragma unroll
        for (int n = 0; n < 16; ++n)
            s += (sU[tid][n] + __ldg(b2 + n)) * (sU[tid][n + 16] + __ldg(b3 + n));
        g_s[tok0 + tid] = s;
    }
}

// ---------------------------------------------------------------------------
// Kernel 2: main GEMM — A ldmatrix from [m][k], B ldmatrix.trans from [k][n]
// ---------------------------------------------------------------------------
__device__ __forceinline__ void g_prefetch(uint32_t smem_base_u, int stage, int kt,
                                           int m0, int n0, int tid) {
    const uint32_t st = smem_base_u + (uint32_t)(stage * G_STAGE_H) * 2;
#pragma unroll
    for (int i = 0; i < 4; ++i) {           // A: 128 rows x 4 x 16B
        const int c = tid + i * GTHREADS;
        const int row = c >> 2, ch = c & 3;
        cp_async16(st + (uint32_t)(row * PITCH_H + ch * 8) * 2,
                   g_Xh + (size_t)(m0 + row) * DDIM + kt * BK + ch * 8);
    }
#pragma unroll
    for (int i = 0; i < 4; ++i) {           // B: 32 k-rows x 16 x 16B
        const int c = tid + i * GTHREADS;
        const int row = c >> 4, ch = c & 15;
        cp_async16(st + (uint32_t)(A_STAGE_H + row * B_PITCH_H + ch * 8) * 2,
                   g_W1h + (size_t)(kt * BK + row) * DDIM + n0 + ch * 8);
    }
}

__global__ void __launch_bounds__(GTHREADS, 2) s6_gemm(const float* __restrict__ x,
                                                       const float* __restrict__ b1,
                                                       float* __restrict__ y) {
    extern __shared__ __half smh[];
    const uint32_t sm_u = smem_u32(smh);

    const int tid = threadIdx.x;
    const int wid = tid >> 5;
    const int lane = tid & 31;
    const int grp = lane >> 2;
    const int qid = lane & 3;
    const int wm = wid & 1;      // 2 warps along M (64 each)
    const int wn = wid >> 1;     // 2 warps along N (64 each)
    const int m0 = blockIdx.y * BM;
    const int n0 = blockIdx.x * BN;

    const uint32_t aIdx = (uint32_t)((wm * 64 + (lane & 15)) * PITCH_H + (lane >> 4) * 8);
    const uint32_t bIdx = (uint32_t)(A_STAGE_H +
        (((lane >> 3) & 1) * 8 + (lane & 7)) * B_PITCH_H + ((lane >> 4) & 1) * 8 + wn * 64);

    float acc[4][8][4];
#pragma unroll
    for (int f = 0; f < 4; ++f)
#pragma unroll
        for (int g = 0; g < 8; ++g)
#pragma unroll
            for (int q = 0; q < 4; ++q) acc[f][g][q] = 0.0f;

    g_prefetch(sm_u, 0, 0, m0, n0, tid);
    cp_commit();
    g_prefetch(sm_u, 1, 1, m0, n0, tid);
    cp_commit();

    for (int kt = 0; kt < NKIT; ++kt) {
        const int s = kt % STAGES;
        cp_wait<1>();
        __syncthreads();

        const int pf = kt + 2;
        if (pf < NKIT) g_prefetch(sm_u, pf % STAGES, pf, m0, n0, tid);
        cp_commit();

        const uint32_t stg = sm_u + (uint32_t)(s * G_STAGE_H) * 2;
#pragma unroll
        for (int ks = 0; ks < 2; ++ks) {
            uint32_t af[4][4], bf[8][2];
#pragma unroll
            for (int f = 0; f < 4; ++f)
                ldmx4(af[f], stg + (aIdx + (uint32_t)(f * 16 * PITCH_H + ks * 16)) * 2);
#pragma unroll
            for (int h = 0; h < 4; ++h) {
                uint32_t bq[4];
                ldmx4t(bq, stg + (bIdx + (uint32_t)(ks * 16 * B_PITCH_H + h * 16)) * 2);
                bf[2 * h][0]     = bq[0];   // (k lo, n lo)
                bf[2 * h][1]     = bq[1];   // (k hi, n lo)
                bf[2 * h + 1][0] = bq[2];   // (k lo, n hi)
                bf[2 * h + 1][1] = bq[3];   // (k hi, n hi)
            }
#pragma unroll
            for (int f = 0; f < 4; ++f)
#pragma unroll
                for (int g = 0; g < 8; ++g)
                    mma_f16(acc[f][g], af[f], bf[g]);
        }
    }

    // fused epilogue: y = x * softplus(acc + b1) * s
#pragma unroll
    for (int f = 0; f < 4; ++f) {
        const int r0 = m0 + wm * 64 + f * 16 + grp;
        const int r1 = r0 + 8;
        const float s0 = __ldg(g_s + r0);
        const float s1 = __ldg(g_s + r1);
        const float* xr0 = x + (size_t)r0 * DDIM;
        const float* xr1 = x + (size_t)r1 * DDIM;
        float* yr0 = y + (size_t)r0 * DDIM;
        float* yr1 = y + (size_t)r1 * DDIM;
#pragma unroll
        for (int g = 0; g < 8; ++g) {
            const int c = n0 + wn * 64 + g * 8 + 2 * qid;
            const float2 bv = *(const float2*)(b1 + c);
            const float2 x0 = *(const float2*)(xr0 + c);
            const float2 x1 = *(const float2*)(xr1 + c);
            float2 o0, o1;
            o0.x = x0.x * softplus_f(acc[f][g][0] + bv.x) * s0;
            o0.y = x0.y * softplus_f(acc[f][g][1] + bv.y) * s0;
            o1.x = x1.x * softplus_f(acc[f][g][2] + bv.x) * s1;
            o1.y = x1.y * softplus_f(acc[f][g][3] + bv.y) * s1;
            *(float2*)(yr0 + c) = o0;
            *(float2*)(yr1 + c) = o1;
        }
    }
}

// ---------------------------------------------------------------------------
// Launch
// ---------------------------------------------------------------------------
extern "C" void kernel_launch(void* const* d_in, const int* in_sizes, int n_in,
                              void* d_out, int out_size) {
    const float* x  = (const float*)d_in[0];
    const float* W1 = (const float*)d_in[1];
    const float* b1 = (const float*)d_in[2];
    const float* W2 = (const float*)d_in[3];
    const float* b2 = (const float*)d_in[4];
    const float* W3 = (const float*)d_in[5];
    const float* b3 = (const float*)d_in[6];
    float* y = (float*)d_out;

    s6_prep<<<PREP_BLOCKS + COPY_BLOCKS, 256>>>(x, W1, W2, W3, b2, b3);

    cudaFuncSetAttribute(s6_gemm, cudaFuncAttributeMaxDynamicSharedMemorySize, G_SMEM_BYTES);
    s6_gemm<<<dim3(DDIM / BN, NTOK / BM), GTHREADS, G_SMEM_BYTES>>>(x, b1, y);
}

// round 16
// speedup vs baseline: 1.0537x; 1.0537x over previous
#include <cuda_runtime.h>
#include <cuda_fp16.h>
#include <cstdint>

// ============================================================================
// S6 forward, reduced:
//   y[t,d] = x[t,d] * softplus(U1[t,d] + b1[d]) * s[t]
//   s[t]   = sum_n (U2[t,n]+b2[n]) * (U3[t,n]+b3[n])
// Pipeline (fp16 mma.sync, fp32 accum; base sm_103 ISA — no tcgen05):
//   1. pack_w23: W2|W3 -> g_W23h [32][k]  (coalesced float4 reads, 64 CTAs)
//   2. prep+packW1 (ONE kernel): blocks [0,512) = x->fp16 + s[t];
//      blocks [512,768) = W1 fp32->fp16 copy (overlapped with prep)
//   3. gemm: 128x128 CTA, 4 warps @ 64x64, A ldmatrix / B ldmatrix.trans,
//            3-stage cp.async, fused epilogue -> y
// ============================================================================

#define NTOK   8192
#define DDIM   1024

#define BM     128
#define BN     128
#define BK     32
#define NKIT   (DDIM / BK)   // 32
#define GTHREADS 128         // 4 warps, 2x2 warp grid, 64x64 per warp

#define PITCH_H   40         // A smem row pitch (halves) = 80B
#define B_PITCH_H 136        // B smem row pitch (halves) = 272B; trans-ldm conflict-free
#define A_STAGE_H (BM * PITCH_H)               // 5120 halves
#define B_STAGE_H (BK * B_PITCH_H)             // 4352 halves
#define G_STAGE_H (A_STAGE_H + B_STAGE_H)      // 9472
#define STAGES    3
#define G_SMEM_BYTES (STAGES * G_STAGE_H * 2)  // 56832

#define PREP_BLOCKS 512
#define COPY_BLOCKS 256       // 262144 float4 / 1024 per block

__device__ __half g_W1h[(size_t)DDIM * DDIM];  // W1, [k][n], fp16, 2 MB
__device__ __half g_W23h[32 * DDIM];           // [n][k]: n<16 W2 col, n>=16 W3 col
__device__ __half g_Xh[(size_t)NTOK * DDIM];   // x fp16, 16.8 MB
__device__ float  g_s[NTOK];

// ---------------------------------------------------------------------------
// helpers
// ---------------------------------------------------------------------------
__device__ __forceinline__ uint32_t smem_u32(const void* p) {
    uint32_t a;
    asm("{ .reg .u64 t; cvta.to.shared.u64 t, %1; cvt.u32.u64 %0, t; }" : "=r"(a) : "l"(p));
    return a;
}
__device__ __forceinline__ uint32_t h2_u32(__half2 h) {
    union { __half2 h; uint32_t u; } cvt;
    cvt.h = h;
    return cvt.u;
}
__device__ __forceinline__ void cp_async16(uint32_t dst, const void* src) {
    asm volatile("cp.async.cg.shared.global [%0], [%1], 16;" :: "r"(dst), "l"(src) : "memory");
}
__device__ __forceinline__ void cp_commit() {
    asm volatile("cp.async.commit_group;" ::: "memory");
}
template <int N>
__device__ __forceinline__ void cp_wait() {
    asm volatile("cp.async.wait_group %0;" :: "n"(N) : "memory");
}
__device__ __forceinline__ void ldmx4(uint32_t* r, uint32_t addr) {
    asm volatile("ldmatrix.sync.aligned.m8n8.x4.shared.b16 {%0,%1,%2,%3}, [%4];"
        : "=r"(r[0]), "=r"(r[1]), "=r"(r[2]), "=r"(r[3]) : "r"(addr));
}
__device__ __forceinline__ void ldmx4t(uint32_t* r, uint32_t addr) {
    asm volatile("ldmatrix.sync.aligned.m8n8.x4.trans.shared.b16 {%0,%1,%2,%3}, [%4];"
        : "=r"(r[0]), "=r"(r[1]), "=r"(r[2]), "=r"(r[3]) : "r"(addr));
}
__device__ __forceinline__ void mma_f16(float* c, const uint32_t* a, const uint32_t* b) {
    asm volatile(
        "mma.sync.aligned.m16n8k16.row.col.f32.f16.f16.f32 "
        "{%0,%1,%2,%3}, {%4,%5,%6,%7}, {%8,%9}, {%0,%1,%2,%3};"
        : "+f"(c[0]), "+f"(c[1]), "+f"(c[2]), "+f"(c[3])
        : "r"(a[0]), "r"(a[1]), "r"(a[2]), "r"(a[3]), "r"(b[0]), "r"(b[1]));
}
__device__ __forceinline__ float softplus_f(float z) {
    return fmaxf(z, 0.0f) + __logf(1.0f + __expf(-fabsf(z)));
}

// ---------------------------------------------------------------------------
// Kernel 1: pack_w23 — coalesced: each thread reads one float4 (k, n-quad)
//   8192 threads: idx>>12 selects W2/W3; k = (idx&4095)>>2; nq = idx&3
// ---------------------------------------------------------------------------
__global__ void __launch_bounds__(128) s6_pack_w23(const float* __restrict__ W2,
                                                   const float* __restrict__ W3) {
    const int idx = blockIdx.x * 128 + threadIdx.x;   // 0..8191
    const int mat = idx >> 12;                        // 0: W2, 1: W3
    const int rem = idx & 4095;
    const int k = rem >> 2;
    const int nq = (rem & 3) * 4;
    const float4 v = *(const float4*)((mat ? W3 : W2) + (size_t)k * 16 + nq);
    const int nb = mat * 16 + nq;
    g_W23h[(nb + 0) * DDIM + k] = __float2half_rn(v.x);
    g_W23h[(nb + 1) * DDIM + k] = __float2half_rn(v.y);
    g_W23h[(nb + 2) * DDIM + k] = __float2half_rn(v.z);
    g_W23h[(nb + 3) * DDIM + k] = __float2half_rn(v.w);
}

// ---------------------------------------------------------------------------
// Kernel 2: prep + W1 pack, one launch.
//   blocks [0,512):   fused x->fp16 convert + s[t], 16 tokens each
//   blocks [512,768): W1 fp32->fp16 copy, 4 float4 per thread
// ---------------------------------------------------------------------------
#define P_PITCH 136
#define PX_STG  (16 * P_PITCH)
#define PW_STG  (32 * P_PITCH)

__global__ void __launch_bounds__(256) s6_prep(const float* __restrict__ x,
                                               const float* __restrict__ W1,
                                               const float* __restrict__ b2,
                                               const float* __restrict__ b3) {
    __shared__ __half sX[2][PX_STG];
    __shared__ __half sW[2][PW_STG];
    __shared__ float sU[16][33];

    const int tid = threadIdx.x;

    if (blockIdx.x >= PREP_BLOCKS) {
        // ---- W1 copy path (overlaps prep blocks) ----
        const int rel = blockIdx.x - PREP_BLOCKS;
#pragma unroll
        for (int i = 0; i < 4; ++i) {
            const size_t i4 = (size_t)rel * 1024 + i * 256 + tid;
            const float4 v = ((const float4*)W1)[i4];
            uint2 pk;
            pk.x = h2_u32(__float22half2_rn(make_float2(v.x, v.y)));
            pk.y = h2_u32(__float22half2_rn(make_float2(v.z, v.w)));
            ((uint2*)g_W1h)[i4] = pk;
        }
        return;
    }

    // ---- prep path ----
    const int wid = tid >> 5;
    const int lane = tid & 31;
    const int grp = lane >> 2;
    const int qid = lane & 3;
    const int tok0 = blockIdx.x * 16;
    const uint32_t sW_u[2] = { smem_u32(sW[0]), smem_u32(sW[1]) };

    for (int i = tid; i < 16 * 33; i += 256) ((float*)sU)[i] = 0.0f;

#pragma unroll
    for (int j = 0; j < 2; ++j) {
        const int i = tid + j * 256;
        const int row = i >> 4, ch = i & 15;
        cp_async16(sW_u[0] + (uint32_t)(row * P_PITCH + ch * 8) * 2,
                   g_W23h + row * DDIM + ch * 8);
    }
    cp_commit();

    const int t = tid >> 4;
    const int co = (tid & 15) * 8;

    float acc[4][4];
#pragma unroll
    for (int g = 0; g < 4; ++g)
#pragma unroll
        for (int q = 0; q < 4; ++q) acc[g][q] = 0.0f;

    for (int c = 0; c < 8; ++c) {
        const int st = c & 1;
        const float* src = x + (size_t)(tok0 + t) * DDIM + c * 128 + co;
        float4 v0 = *(const float4*)(src + 0);
        float4 v1 = *(const float4*)(src + 4);
        uint4 pk;
        pk.x = h2_u32(__float22half2_rn(make_float2(v0.x, v0.y)));
        pk.y = h2_u32(__float22half2_rn(make_float2(v0.z, v0.w)));
        pk.z = h2_u32(__float22half2_rn(make_float2(v1.x, v1.y)));
        pk.w = h2_u32(__float22half2_rn(make_float2(v1.z, v1.w)));
        *(uint4*)(&sX[st][t * P_PITCH + co]) = pk;
        *(uint4*)(g_Xh + (size_t)(tok0 + t) * DDIM + c * 128 + co) = pk;

        cp_wait<0>();
        __syncthreads();

        if (c < 7) {
            const int ns = (c + 1) & 1;
#pragma unroll
            for (int j = 0; j < 2; ++j) {
                const int i = tid + j * 256;
                const int row = i >> 4, ch = i & 15;
                cp_async16(sW_u[ns] + (uint32_t)(row * P_PITCH + ch * 8) * 2,
                           g_W23h + row * DDIM + (c + 1) * 128 + ch * 8);
            }
            cp_commit();
        }

        const int koff = wid * 16 + 2 * qid;
        {
            const __half* p = &sX[st][grp * P_PITCH + koff];
            uint32_t a[4];
            a[0] = *(const uint32_t*)p;
            a[1] = *(const uint32_t*)(p + 8 * P_PITCH);
            a[2] = *(const uint32_t*)(p + 8);
            a[3] = *(const uint32_t*)(p + 8 * P_PITCH + 8);
#pragma unroll
            for (int g = 0; g < 4; ++g) {
                const __half* q = &sW[st][(g * 8 + grp) * P_PITCH + koff];
                uint32_t b[2];
                b[0] = *(const uint32_t*)q;
                b[1] = *(const uint32_t*)(q + 8);
                mma_f16(acc[g], a, b);
            }
        }
        __syncthreads();
    }

#pragma unroll
    for (int g = 0; g < 4; ++g) {
        atomicAdd(&sU[grp][g * 8 + 2 * qid],         acc[g][0]);
        atomicAdd(&sU[grp][g * 8 + 2 * qid + 1],     acc[g][1]);
        atomicAdd(&sU[grp + 8][g * 8 + 2 * qid],     acc[g][2]);
        atomicAdd(&sU[grp + 8][g * 8 + 2 * qid + 1], acc[g][3]);
    }
    __syncthreads();

    if (tid < 16) {
        float s = 0.0f;
#pragma unroll
        for (int n = 0; n < 16; ++n)
            s += (sU[tid][n] + __ldg(b2 + n)) * (sU[tid][n + 16] + __ldg(b3 + n));
        g_s[tok0 + tid] = s;
    }
}

// ---------------------------------------------------------------------------
// Kernel 3: main GEMM — A ldmatrix from [m][k], B ldmatrix.trans from [k][n]
// ---------------------------------------------------------------------------
__device__ __forceinline__ void g_prefetch(uint32_t smem_base_u, int stage, int kt,
                                           int m0, int n0, int tid) {
    const uint32_t st = smem_base_u + (uint32_t)(stage * G_STAGE_H) * 2;
#pragma unroll
    for (int i = 0; i < 4; ++i) {           // A: 128 rows x 4 x 16B
        const int c = tid + i * GTHREADS;
        const int row = c >> 2, ch = c & 3;
        cp_async16(st + (uint32_t)(row * PITCH_H + ch * 8) * 2,
                   g_Xh + (size_t)(m0 + row) * DDIM + kt * BK + ch * 8);
    }
#pragma unroll
    for (int i = 0; i < 4; ++i) {           // B: 32 k-rows x 16 x 16B
        const int c = tid + i * GTHREADS;
        const int row = c >> 4, ch = c & 15;
        cp_async16(st + (uint32_t)(A_STAGE_H + row * B_PITCH_H + ch * 8) * 2,
                   g_W1h + (size_t)(kt * BK + row) * DDIM + n0 + ch * 8);
    }
}

__global__ void __launch_bounds__(GTHREADS, 2) s6_gemm(const float* __restrict__ x,
                                                       const float* __restrict__ b1,
                                                       float* __restrict__ y) {
    extern __shared__ __half smh[];
    const uint32_t sm_u = smem_u32(smh);

    const int tid = threadIdx.x;
    const int wid = tid >> 5;
    const int lane = tid & 31;
    const int grp = lane >> 2;
    const int qid = lane & 3;
    const int wm = wid & 1;      // 2 warps along M (64 each)
    const int wn = wid >> 1;     // 2 warps along N (64 each)
    const int m0 = blockIdx.y * BM;
    const int n0 = blockIdx.x * BN;

    const uint32_t aIdx = (uint32_t)((wm * 64 + (lane & 15)) * PITCH_H + (lane >> 4) * 8);
    const uint32_t bIdx = (uint32_t)(A_STAGE_H +
        (((lane >> 3) & 1) * 8 + (lane & 7)) * B_PITCH_H + ((lane >> 4) & 1) * 8 + wn * 64);

    float acc[4][8][4];
#pragma unroll
    for (int f = 0; f < 4; ++f)
#pragma unroll
        for (int g = 0; g < 8; ++g)
#pragma unroll
            for (int q = 0; q < 4; ++q) acc[f][g][q] = 0.0f;

    g_prefetch(sm_u, 0, 0, m0, n0, tid);
    cp_commit();
    g_prefetch(sm_u, 1, 1, m0, n0, tid);
    cp_commit();

    for (int kt = 0; kt < NKIT; ++kt) {
        const int s = kt % STAGES;
        cp_wait<1>();
        __syncthreads();

        const int pf = kt + 2;
        if (pf < NKIT) g_prefetch(sm_u, pf % STAGES, pf, m0, n0, tid);
        cp_commit();

        const uint32_t stg = sm_u + (uint32_t)(s * G_STAGE_H) * 2;
#pragma unroll
        for (int ks = 0; ks < 2; ++ks) {
            uint32_t af[4][4], bf[8][2];
#pragma unroll
            for (int f = 0; f < 4; ++f)
                ldmx4(af[f], stg + (aIdx + (uint32_t)(f * 16 * PITCH_H + ks * 16)) * 2);
#pragma unroll
            for (int h = 0; h < 4; ++h) {
                uint32_t bq[4];
                ldmx4t(bq, stg + (bIdx + (uint32_t)(ks * 16 * B_PITCH_H + h * 16)) * 2);
                bf[2 * h][0]     = bq[0];   // (k lo, n lo)
                bf[2 * h][1]     = bq[1];   // (k hi, n lo)
                bf[2 * h + 1][0] = bq[2];   // (k lo, n hi)
                bf[2 * h + 1][1] = bq[3];   // (k hi, n hi)
            }
#pragma unroll
            for (int f = 0; f < 4; ++f)
#pragma unroll
                for (int g = 0; g < 8; ++g)
                    mma_f16(acc[f][g], af[f], bf[g]);
        }
    }

    // fused epilogue: y = x * softplus(acc + b1) * s
#pragma unroll
    for (int f = 0; f < 4; ++f) {
        const int r0 = m0 + wm * 64 + f * 16 + grp;
        const int r1 = r0 + 8;
        const float s0 = __ldg(g_s + r0);
        const float s1 = __ldg(g_s + r1);
        const float* xr0 = x + (size_t)r0 * DDIM;
        const float* xr1 = x + (size_t)r1 * DDIM;
        float* yr0 = y + (size_t)r0 * DDIM;
        float* yr1 = y + (size_t)r1 * DDIM;
#pragma unroll
        for (int g = 0; g < 8; ++g) {
            const int c = n0 + wn * 64 + g * 8 + 2 * qid;
            const float2 bv = *(const float2*)(b1 + c);
            const float2 x0 = *(const float2*)(xr0 + c);
            const float2 x1 = *(const float2*)(xr1 + c);
            float2 o0, o1;
            o0.x = x0.x * softplus_f(acc[f][g][0] + bv.x) * s0;
            o0.y = x0.y * softplus_f(acc[f][g][1] + bv.y) * s0;
            o1.x = x1.x * softplus_f(acc[f][g][2] + bv.x) * s1;
            o1.y = x1.y * softplus_f(acc[f][g][3] + bv.y) * s1;
            *(float2*)(yr0 + c) = o0;
            *(float2*)(yr1 + c) = o1;
        }
    }
}

// ---------------------------------------------------------------------------
// Launch
// ---------------------------------------------------------------------------
extern "C" void kernel_launch(void* const* d_in, const int* in_sizes, int n_in,
                              void* d_out, int out_size) {
    const float* x  = (const float*)d_in[0];
    const float* W1 = (const float*)d_in[1];
    const float* b1 = (const float*)d_in[2];
    const float* W2 = (const float*)d_in[3];
    const float* b2 = (const float*)d_in[4];
    const float* W3 = (const float*)d_in[5];
    const float* b3 = (const float*)d_in[6];
    float* y = (float*)d_out;

    s6_pack_w23<<<64, 128>>>(W2, W3);
    s6_prep<<<PREP_BLOCKS + COPY_BLOCKS, 256>>>(x, W1, b2, b3);

    cudaFuncSetAttribute(s6_gemm, cudaFuncAttributeMaxDynamicSharedMemorySize, G_SMEM_BYTES);
    s6_gemm<<<dim3(DDIM / BN, NTOK / BM), GTHREADS, G_SMEM_BYTES>>>(x, b1, y);
}